// round 1
// baseline (speedup 1.0000x reference)
#include <cuda_runtime.h>
#include <math.h>

#define PP 4
#define BB 128
#define DD 512
#define NN 32768
#define KKc 10
#define NT 256          // NN / 128 tiles
#define NEG_INF_F (-1e30f)
#define SIM_TH_F 0.7f
#define SCALE_F 10.0f

// ---------------- scratch (device globals; no allocations allowed) ----------
__device__ float g_img[PP*BB*DD];        // normalized feature
__device__ float g_txt[PP*BB*DD];        // normalized transposed text
__device__ float g_fn2[PP*BB];           // ||feature||^2 (unnormalized)
__device__ float g_img_sim[PP*BB*BB];
__device__ float g_txt_sim[PP*BB*BB];
__device__ int   g_valid[PP*BB];
__device__ float g_kl1[PP*BB];
__device__ float g_kl2[PP*BB];
__device__ float g_x[PP*BB];             // pos logsumexp term
__device__ float g_partial[PP*NT*BB];    // per-tile neg sums (deterministic)
__device__ unsigned char g_negmask[NN];

// ---------------- reduction helpers (blockDim.x == 128) ---------------------
__device__ __forceinline__ float warpSum(float v){
    #pragma unroll
    for (int o=16;o;o>>=1) v += __shfl_xor_sync(0xffffffffu, v, o);
    return v;
}
__device__ __forceinline__ float warpMax(float v){
    #pragma unroll
    for (int o=16;o;o>>=1) v = fmaxf(v, __shfl_xor_sync(0xffffffffu, v, o));
    return v;
}
__device__ float blockSum128(float v){
    __shared__ float sh[4];
    int w = threadIdx.x>>5, l = threadIdx.x&31;
    v = warpSum(v);
    __syncthreads();
    if (l==0) sh[w] = v;
    __syncthreads();
    return sh[0]+sh[1]+sh[2]+sh[3];
}
__device__ float blockMax128(float v){
    __shared__ float sh[4];
    int w = threadIdx.x>>5, l = threadIdx.x&31;
    v = warpMax(v);
    __syncthreads();
    if (l==0) sh[w] = v;
    __syncthreads();
    return fmaxf(fmaxf(sh[0],sh[1]), fmaxf(sh[2],sh[3]));
}

// ---------------- mask init + scatter ---------------------------------------
__global__ void mask_init_kernel(){
    int i = blockIdx.x*blockDim.x + threadIdx.x;
    if (i < NN) g_negmask[i] = 1;
}
__global__ void mask_scatter_kernel(const int* __restrict__ cross_indices,
                                    const int* __restrict__ position){
    int i = blockIdx.x*blockDim.x + threadIdx.x;
    if (i < BB*KKc)       g_negmask[cross_indices[i]] = 0;
    else if (i < BB*KKc+BB) g_negmask[position[i - BB*KKc]] = 0;
}

// ---------------- normalize + fn2 -------------------------------------------
// grid = P*B blocks, 128 threads
__global__ void normalize_kernel(const float* __restrict__ feature,
                                 const float* __restrict__ text_feature){
    int p = blockIdx.x / BB, b = blockIdx.x % BB;
    int tid = threadIdx.x;
    const float* f = feature + (size_t)(p*BB + b)*DD;
    const float* t = text_feature + (size_t)(b*PP + p)*DD;
    float sf = 0.f, st = 0.f;
    for (int d = tid; d < DD; d += 128){ float v=f[d]; sf += v*v; float w=t[d]; st += w*w; }
    __shared__ float sh[8];
    int w = tid>>5, l = tid&31;
    sf = warpSum(sf); st = warpSum(st);
    if (l==0){ sh[w]=sf; sh[4+w]=st; }
    __syncthreads();
    float fn2 = sh[0]+sh[1]+sh[2]+sh[3];
    float tn2 = sh[4]+sh[5]+sh[6]+sh[7];
    if (tid==0) g_fn2[p*BB+b] = fn2;
    float invf = 1.f / fmaxf(sqrtf(fn2), 1e-12f);
    float invt = 1.f / fmaxf(sqrtf(tn2), 1e-12f);
    float* oi = g_img + (size_t)(p*BB+b)*DD;
    float* ot = g_txt + (size_t)(p*BB+b)*DD;
    for (int d = tid; d < DD; d += 128){ oi[d] = f[d]*invf; ot[d] = t[d]*invt; }
}

// ---------------- similarity rows + valid ------------------------------------
// grid = P*B blocks (row b), 128 threads (one per column c)
__global__ void sim_kernel(){
    int p = blockIdx.x / BB, b = blockIdx.x % BB;
    int tid = threadIdx.x;
    __shared__ float si[DD], st[DD];
    const float* ri = g_img + (size_t)(p*BB+b)*DD;
    const float* rt = g_txt + (size_t)(p*BB+b)*DD;
    for (int d = tid; d < DD; d += 128){ si[d] = ri[d]; st[d] = rt[d]; }
    __syncthreads();
    int c = tid;
    const float4* ic = (const float4*)(g_img + (size_t)(p*BB+c)*DD);
    const float4* tc = (const float4*)(g_txt + (size_t)(p*BB+c)*DD);
    const float4* si4 = (const float4*)si;
    const float4* st4 = (const float4*)st;
    float di = 0.f, dt = 0.f;
    #pragma unroll 8
    for (int d4 = 0; d4 < DD/4; d4++){
        float4 a = si4[d4], x = ic[d4];
        di += a.x*x.x + a.y*x.y + a.z*x.z + a.w*x.w;
        float4 bv = st4[d4], y = tc[d4];
        dt += bv.x*y.x + bv.y*y.y + bv.z*y.z + bv.w*y.w;
    }
    di *= 2.0f; dt *= 2.0f;   // / TEMP (0.5)
    g_img_sim[((size_t)(p*BB+b))*BB + c] = di;
    g_txt_sim[((size_t)(p*BB+b))*BB + c] = dt;
    int m = (di > SIM_TH_F) && (dt > SIM_TH_F);
    int valid = __syncthreads_or(m);
    if (tid == 0) g_valid[p*BB+b] = valid;
}

// ---------------- masked softmax + KL per row --------------------------------
// grid = P*B blocks (row b), 128 threads (column c)
__global__ void kl_kernel(){
    int p = blockIdx.x / BB, b = blockIdx.x % BB;
    int c = threadIdx.x;
    float is = g_img_sim[((size_t)(p*BB+b))*BB + c];
    float ts = g_txt_sim[((size_t)(p*BB+b))*BB + c];
    int colm = g_valid[p*BB + c];
    float il = colm ? is : NEG_INF_F;
    float tl = colm ? ts : NEG_INF_F;
    float mi = blockMax128(il);
    float sumi = blockSum128(expf(il - mi));
    float lsei = mi + logf(sumi);
    float mt = blockMax128(tl);
    float sumt = blockSum128(expf(tl - mt));
    float lset = mt + logf(sumt);
    float img_logp = il - lsei;
    float txt_logp = tl - lset;
    float k1 = colm ? expf(txt_logp) * (txt_logp - img_logp) : 0.f;
    float k2 = colm ? expf(img_logp) * (img_logp - txt_logp) : 0.f;
    float s1 = blockSum128(k1);
    float s2 = blockSum128(k2);
    if (c == 0){
        int rv = g_valid[p*BB + b];
        g_kl1[p*BB+b] = rv ? s1 : 0.f;
        g_kl2[p*BB+b] = rv ? s2 : 0.f;
    }
}

// ---------------- big fused GEMM: neg distances ------------------------------
// 128x128 tile per block, 256 threads, 8x8 micro-tile; cn2 fused from B tile;
// epilogue computes masked exp(-10*dist) and reduces per-b deterministically.
__global__ __launch_bounds__(256) void neg_gemm_kernel(const float* __restrict__ feature,
                                                       const float* __restrict__ centers){
    const int p  = blockIdx.y;
    const int n0 = blockIdx.x * 128;
    __shared__ float sA[32*132];
    __shared__ float sB[32*132];
    const int tid = threadIdx.x;
    const int tx = tid & 15, ty = tid >> 4;
    float acc[8][8]; float sq[8];
    #pragma unroll
    for (int i=0;i<8;i++){ sq[i]=0.f;
        #pragma unroll
        for (int j=0;j<8;j++) acc[i][j]=0.f; }
    const float* Abase = feature + (size_t)p*BB*DD;
    const float* Bbase = centers + (size_t)p*NN*DD + (size_t)n0*DD;
    for (int k0 = 0; k0 < DD; k0 += 32){
        #pragma unroll
        for (int l = 0; l < 4; l++){
            int e = l*256 + tid; int row = e >> 3; int c4 = e & 7;
            float4 va = *(const float4*)(Abase + (size_t)row*DD + k0 + c4*4);
            float4 vb = *(const float4*)(Bbase + (size_t)row*DD + k0 + c4*4);
            int c = c4*4;
            sA[(c+0)*132+row]=va.x; sA[(c+1)*132+row]=va.y; sA[(c+2)*132+row]=va.z; sA[(c+3)*132+row]=va.w;
            sB[(c+0)*132+row]=vb.x; sB[(c+1)*132+row]=vb.y; sB[(c+2)*132+row]=vb.z; sB[(c+3)*132+row]=vb.w;
        }
        __syncthreads();
        #pragma unroll 4
        for (int kk = 0; kk < 32; kk++){
            float4 a0 = *(const float4*)&sA[kk*132 + ty*8];
            float4 a1 = *(const float4*)&sA[kk*132 + ty*8 + 4];
            float4 b0 = *(const float4*)&sB[kk*132 + tx*8];
            float4 b1 = *(const float4*)&sB[kk*132 + tx*8 + 4];
            float a[8] = {a0.x,a0.y,a0.z,a0.w,a1.x,a1.y,a1.z,a1.w};
            float bb[8]= {b0.x,b0.y,b0.z,b0.w,b1.x,b1.y,b1.z,b1.w};
            #pragma unroll
            for (int j=0;j<8;j++) sq[j] += bb[j]*bb[j];
            #pragma unroll
            for (int i=0;i<8;i++)
                #pragma unroll
                for (int j=0;j<8;j++) acc[i][j] += a[i]*bb[j];
        }
        __syncthreads();
    }
    float fn2b[8], partial[8];
    #pragma unroll
    for (int i=0;i<8;i++){ fn2b[i] = g_fn2[p*BB + ty*8 + i]; partial[i] = 0.f; }
    #pragma unroll
    for (int j=0;j<8;j++){
        int n = n0 + tx*8 + j;
        float m = g_negmask[n] ? 1.f : 0.f;
        float cn2 = sq[j];
        #pragma unroll
        for (int i=0;i<8;i++){
            float nd2 = fn2b[i] + cn2 - 2.f*acc[i][j];
            float d = sqrtf(fmaxf(nd2, 1e-12f));
            partial[i] += m * expf(-SCALE_F * d);
        }
    }
    float* red = sA;  // reuse smem: [128][16]
    #pragma unroll
    for (int i=0;i<8;i++) red[(ty*8+i)*16 + tx] = partial[i];
    __syncthreads();
    if (tid < 128){
        float s = 0.f;
        #pragma unroll
        for (int t=0;t<16;t++) s += red[tid*16 + t];
        g_partial[((size_t)p*NT + blockIdx.x)*BB + tid] = s;
    }
}

// ---------------- positive term ----------------------------------------------
// grid = P*B blocks, 32 threads (one warp)
__global__ void pos_kernel(const float* __restrict__ feature,
                           const float* __restrict__ centers,
                           const int* __restrict__ cross_indices){
    int p = blockIdx.x / BB, b = blockIdx.x % BB;
    int lane = threadIdx.x;
    const float* f = feature + (size_t)(p*BB+b)*DD;
    float fn2 = g_fn2[p*BB+b];
    float ssum = 0.f;
    for (int k = 0; k < KKc; k++){
        int idx = cross_indices[b*KKc + k];
        const float* c = centers + ((size_t)p*NN + idx)*DD;
        float dot = 0.f, sqv = 0.f;
        for (int d = lane; d < DD; d += 32){
            float cv = c[d];
            dot += f[d]*cv;
            sqv += cv*cv;
        }
        dot = warpSum(dot);
        sqv = warpSum(sqv);
        float pd2 = fn2 + sqv - 2.f*dot;
        float dist = sqrtf(fmaxf(pd2, 1e-12f));
        ssum += expf(-SCALE_F * dist);
    }
    if (lane == 0) g_x[p*BB+b] = logf(ssum);
}

// ---------------- pos_vid gather ---------------------------------------------
__global__ void posvid_kernel(const int* __restrict__ cross_indices,
                              const int* __restrict__ vid,
                              float* __restrict__ out, int out_size){
    int i = blockIdx.x*blockDim.x + threadIdx.x;
    if (i < BB*KKc && (3 + i) < out_size)
        out[3 + i] = (float)vid[cross_indices[i]];
}

// ---------------- final combine ----------------------------------------------
// 1 block, 128 threads (thread index = b)
__global__ void final_kernel(float* __restrict__ out, int out_size){
    int b = threadIdx.x;
    // contrastive
    float closs = 0.f;
    for (int p = 0; p < PP; p++){
        float ns = 0.f;
        for (int t = 0; t < NT; t++)
            ns += g_partial[((size_t)p*NT + t)*BB + b];
        float y = logf(ns);
        float v = y - g_x[p*BB + b];
        float s = blockSum128(v);
        float lp = s / (float)BB;
        if (isnan(lp)) lp = 0.f;
        closs += lp;
    }
    closs /= (float)PP;
    // align
    float aloss = 0.f;
    for (int p = 0; p < PP; p++){
        float nv = blockSum128((float)g_valid[p*BB + b]);
        float s1 = blockSum128(g_kl1[p*BB + b]);
        float s2 = blockSum128(g_kl2[p*BB + b]);
        float pp = 0.5f * (s1 + s2) / fmaxf(nv, 1.f);
        if (nv > 0.f) aloss += pp;
    }
    float klw = fmaxf(0.5f * (1.f - 1.f/60.f), 0.1f);
    float total = closs + klw * aloss;
    if (b == 0 && out_size >= 3){
        out[0] = total;
        out[1] = closs;
        out[2] = aloss;
    }
}

// ---------------- launch ------------------------------------------------------
extern "C" void kernel_launch(void* const* d_in, const int* in_sizes, int n_in,
                              void* d_out, int out_size){
    const float* feature       = (const float*)d_in[0];
    const float* text_feature  = (const float*)d_in[1];
    const float* centers       = (const float*)d_in[2];
    const int*   position      = (const int*)d_in[3];
    const int*   cross_indices = (const int*)d_in[4];
    const int*   vid           = (const int*)d_in[5];
    float* out = (float*)d_out;

    mask_init_kernel<<<NN/256, 256>>>();
    mask_scatter_kernel<<<(BB*KKc + BB + 255)/256, 256>>>(cross_indices, position);
    normalize_kernel<<<PP*BB, 128>>>(feature, text_feature);
    sim_kernel<<<PP*BB, 128>>>();
    kl_kernel<<<PP*BB, 128>>>();
    neg_gemm_kernel<<<dim3(NT, PP), 256>>>(feature, centers);
    pos_kernel<<<PP*BB, 32>>>(feature, centers, cross_indices);
    posvid_kernel<<<(BB*KKc + 255)/256, 256>>>(cross_indices, vid, out, out_size);
    final_kernel<<<1, 128>>>(out, out_size);
}

// round 3
// speedup vs baseline: 1.8023x; 1.8023x over previous
#include <cuda_runtime.h>
#include <cuda_bf16.h>
#include <cstdint>
#include <math.h>

#define PP 4
#define BB 128
#define DD 512
#define NN 32768
#define KKc 10
#define NT 256          // NN / 128 tiles
#define NEG_INF_F (-1e30f)
#define SIM_TH_F 0.7f
#define SCALE_F 10.0f

// ---------------- scratch (device globals) -----------------------------------
__device__ float g_imgT[PP*DD*BB];       // normalized feature, [p][d][b]
__device__ float g_txtT[PP*DD*BB];       // normalized text (transposed), [p][d][b]
__device__ float g_invI[PP*BB];
__device__ float g_invT[PP*BB];
__device__ float g_fn2[PP*BB];
__device__ float g_img_sim[PP*BB*BB];
__device__ float g_txt_sim[PP*BB*BB];
__device__ int   g_valid[PP*BB];
__device__ float g_kl1[PP*BB];
__device__ float g_kl2[PP*BB];
__device__ float g_x[PP*BB];
__device__ float g_partial[PP*NT*BB];
__device__ unsigned char g_negmask[NN];

// ---------------- warp helpers ------------------------------------------------
__device__ __forceinline__ float warpSum(float v){
    #pragma unroll
    for (int o=16;o;o>>=1) v += __shfl_xor_sync(0xffffffffu, v, o);
    return v;
}
__device__ __forceinline__ float warpMax(float v){
    #pragma unroll
    for (int o=16;o;o>>=1) v = fmaxf(v, __shfl_xor_sync(0xffffffffu, v, o));
    return v;
}
__device__ float blockSum128(float v){
    __shared__ float sh[4];
    int w = threadIdx.x>>5, l = threadIdx.x&31;
    v = warpSum(v);
    __syncthreads();
    if (l==0) sh[w] = v;
    __syncthreads();
    return sh[0]+sh[1]+sh[2]+sh[3];
}
__device__ float blockMax128(float v){
    __shared__ float sh[4];
    int w = threadIdx.x>>5, l = threadIdx.x&31;
    v = warpMax(v);
    __syncthreads();
    if (l==0) sh[w] = v;
    __syncthreads();
    return fmaxf(fmaxf(sh[0],sh[1]), fmaxf(sh[2],sh[3]));
}
__device__ __forceinline__ uint32_t smem_u32(const void* p){
    uint32_t a;
    asm("{ .reg .u64 t; cvta.to.shared.u64 t, %1; cvt.u32.u64 %0, t; }" : "=r"(a) : "l"(p));
    return a;
}
__device__ __forceinline__ void ldsm_x4(uint32_t* r, uint32_t addr){
    asm volatile("ldmatrix.sync.aligned.m8n8.x4.shared.b16 {%0,%1,%2,%3}, [%4];"
                 : "=r"(r[0]), "=r"(r[1]), "=r"(r[2]), "=r"(r[3]) : "r"(addr));
}
__device__ __forceinline__ void mma16816(float* c, const uint32_t* a, const uint32_t* b){
    asm volatile("mma.sync.aligned.m16n8k16.row.col.f32.bf16.bf16.f32 "
                 "{%0,%1,%2,%3}, {%4,%5,%6,%7}, {%8,%9}, {%0,%1,%2,%3};"
                 : "+f"(c[0]), "+f"(c[1]), "+f"(c[2]), "+f"(c[3])
                 : "r"(a[0]), "r"(a[1]), "r"(a[2]), "r"(a[3]), "r"(b[0]), "r"(b[1]));
}

// ---------------- mask init + scatter ---------------------------------------
__global__ void mask_init_kernel(){
    int i = blockIdx.x*blockDim.x + threadIdx.x;
    if (i < NN) g_negmask[i] = 1;
}
__global__ void mask_scatter_kernel(const int* __restrict__ cross_indices,
                                    const int* __restrict__ position){
    int i = blockIdx.x*blockDim.x + threadIdx.x;
    if (i < BB*KKc)       g_negmask[cross_indices[i]] = 0;
    else if (i < BB*KKc+BB) g_negmask[position[i - BB*KKc]] = 0;
}

// ---------------- normalize ---------------------------------------------------
__global__ void normalize_kernel(const float* __restrict__ feature,
                                 const float* __restrict__ text_feature){
    int p = blockIdx.x / BB, b = blockIdx.x % BB;
    int tid = threadIdx.x;
    const float* f = feature + (size_t)(p*BB + b)*DD;
    const float* t = text_feature + (size_t)(b*PP + p)*DD;
    float sf = 0.f, st = 0.f;
    for (int d = tid; d < DD; d += 128){ float v=f[d]; sf += v*v; float w=t[d]; st += w*w; }
    __shared__ float sh[8];
    int w = tid>>5, l = tid&31;
    sf = warpSum(sf); st = warpSum(st);
    if (l==0){ sh[w]=sf; sh[4+w]=st; }
    __syncthreads();
    float fn2 = sh[0]+sh[1]+sh[2]+sh[3];
    float tn2 = sh[4]+sh[5]+sh[6]+sh[7];
    float invf = 1.f / fmaxf(sqrtf(fn2), 1e-12f);
    float invt = 1.f / fmaxf(sqrtf(tn2), 1e-12f);
    if (tid==0){
        g_fn2[p*BB+b] = fn2;
        g_invI[p*BB+b] = invf;
        g_invT[p*BB+b] = invt;
    }
    for (int d = tid; d < DD; d += 128){
        g_imgT[((size_t)p*DD + d)*BB + b] = f[d]*invf;
        g_txtT[((size_t)p*DD + d)*BB + b] = t[d]*invt;
    }
}

// ---------------- sims: Gram tiles with transposed layout --------------------
__global__ __launch_bounds__(256) void sim2_kernel(const float* __restrict__ feature,
                                                   const float* __restrict__ text_feature){
    int p = blockIdx.x, rt = blockIdx.y;
    int tid = threadIdx.x;
    int c = tid & 127, half = tid >> 7;
    __shared__ float sRow[2][8][DD];   // 32KB
    __shared__ int s_val[8];
    for (int e = tid; e < 8*DD; e += 256){
        int r = e >> 9, d = e & (DD-1);
        int b = rt*8 + r;
        sRow[0][r][d] = feature[((size_t)p*BB+b)*DD + d] * g_invI[p*BB+b];
        sRow[1][r][d] = text_feature[((size_t)b*PP+p)*DD + d] * g_invT[p*BB+b];
    }
    if (tid < 8) s_val[tid] = 0;
    __syncthreads();
    float acc[8] = {0,0,0,0,0,0,0,0};
    const float* baseI = g_imgT + (size_t)p*DD*BB;
    const float* baseT = g_txtT + (size_t)p*DD*BB;
    for (int d = 0; d < DD; d += 4){
        float iv0 = baseI[(size_t)(d+0)*BB + c];
        float iv1 = baseI[(size_t)(d+1)*BB + c];
        float iv2 = baseI[(size_t)(d+2)*BB + c];
        float iv3 = baseI[(size_t)(d+3)*BB + c];
        float tv0 = baseT[(size_t)(d+0)*BB + c];
        float tv1 = baseT[(size_t)(d+1)*BB + c];
        float tv2 = baseT[(size_t)(d+2)*BB + c];
        float tv3 = baseT[(size_t)(d+3)*BB + c];
        #pragma unroll
        for (int r = 0; r < 4; r++){
            float4 a = *(const float4*)&sRow[0][half*4+r][d];
            acc[r]   += a.x*iv0 + a.y*iv1 + a.z*iv2 + a.w*iv3;
            float4 bb = *(const float4*)&sRow[1][half*4+r][d];
            acc[4+r] += bb.x*tv0 + bb.y*tv1 + bb.z*tv2 + bb.w*tv3;
        }
    }
    #pragma unroll
    for (int r = 0; r < 4; r++){
        int row = rt*8 + half*4 + r;
        float is = acc[r]*2.0f, ts = acc[4+r]*2.0f;   // / TEMP
        g_img_sim[((size_t)(p*BB+row))*BB + c] = is;
        g_txt_sim[((size_t)(p*BB+row))*BB + c] = ts;
        if (is > SIM_TH_F && ts > SIM_TH_F) s_val[half*4+r] = 1;
    }
    __syncthreads();
    if (tid < 8) g_valid[p*BB + rt*8 + tid] = s_val[tid];
}

// ---------------- masked softmax + KL per row --------------------------------
__global__ void kl_kernel(){
    int p = blockIdx.x / BB, b = blockIdx.x % BB;
    int c = threadIdx.x;
    float is = g_img_sim[((size_t)(p*BB+b))*BB + c];
    float ts = g_txt_sim[((size_t)(p*BB+b))*BB + c];
    int colm = g_valid[p*BB + c];
    float il = colm ? is : NEG_INF_F;
    float tl = colm ? ts : NEG_INF_F;
    float mi = blockMax128(il);
    float sumi = blockSum128(expf(il - mi));
    float lsei = mi + logf(sumi);
    float mt = blockMax128(tl);
    float sumt = blockSum128(expf(tl - mt));
    float lset = mt + logf(sumt);
    float img_logp = il - lsei;
    float txt_logp = tl - lset;
    float k1 = colm ? expf(txt_logp) * (txt_logp - img_logp) : 0.f;
    float k2 = colm ? expf(img_logp) * (img_logp - txt_logp) : 0.f;
    float s1 = blockSum128(k1);
    float s2 = blockSum128(k2);
    if (c == 0){
        int rv = g_valid[p*BB + b];
        g_kl1[p*BB+b] = rv ? s1 : 0.f;
        g_kl2[p*BB+b] = rv ? s2 : 0.f;
    }
}

// ---------------- neg distances: bf16 HMMA GEMM ------------------------------
// grid (NT, P), 256 threads = 8 warps in 4(M) x 2(N). Per CTA M=128, N=128, K=512.
// smem tiles: [128 rows][40 bf16] (80B stride: conflict-free for ldmatrix).
#define SAELEM 40    // bf16 per smem row (32 + 8 pad)

struct NegSmem {
    __nv_bfloat16 A[BB*SAELEM];
    __nv_bfloat16 B[BB*SAELEM];
    float cn2[BB];
    float mask[BB];
    float red[BB][2];
};

template<bool CN2>
__device__ __forceinline__ void load_tile(const float* __restrict__ gbase, int k0,
                                          __nv_bfloat16* sdst, float* s_cn2, int tid){
    int lane = tid & 31;
    #pragma unroll
    for (int it = 0; it < 4; it++){
        int idx = it*256 + tid;
        int r = idx >> 3, q = idx & 7;
        float4 v = *(const float4*)(gbase + (size_t)r*DD + k0 + q*4);
        if (CN2){
            float sq = v.x*v.x + v.y*v.y + v.z*v.z + v.w*v.w;
            sq += __shfl_xor_sync(0xffffffffu, sq, 1);
            sq += __shfl_xor_sync(0xffffffffu, sq, 2);
            sq += __shfl_xor_sync(0xffffffffu, sq, 4);
            if ((lane & 7) == 0) s_cn2[r] += sq;
        }
        __nv_bfloat162 h0 = __floats2bfloat162_rn(v.x, v.y);
        __nv_bfloat162 h1 = __floats2bfloat162_rn(v.z, v.w);
        uint2 pk;
        pk.x = *reinterpret_cast<uint32_t*>(&h0);
        pk.y = *reinterpret_cast<uint32_t*>(&h1);
        *reinterpret_cast<uint2*>((char*)sdst + r*(SAELEM*2) + q*8) = pk;
    }
}

__global__ __launch_bounds__(256) void neg_mma_kernel(const float* __restrict__ feature,
                                                      const float* __restrict__ centers){
    __shared__ NegSmem sm;
    const int p = blockIdx.y;
    const int tile = blockIdx.x;
    const int n0g = tile * 128;
    const int tid = threadIdx.x;
    const int wid = tid >> 5, lane = tid & 31;
    const int wm = wid >> 1, wn = wid & 1;       // warp tile: rows wm*32, cols wn*64
    const int l8 = lane & 7, grp = lane >> 3;

    if (tid < BB){
        sm.cn2[tid] = 0.f;
        sm.mask[tid] = g_negmask[n0g + tid] ? 1.f : 0.f;
    }

    const float* Abase = feature + (size_t)p*BB*DD;
    const float* Bbase = centers + ((size_t)p*NN + n0g)*DD;
    const uint32_t sA = smem_u32(sm.A);
    const uint32_t sB = smem_u32(sm.B);

    float acc[2][8][4];
    #pragma unroll
    for (int i=0;i<2;i++)
        #pragma unroll
        for (int j=0;j<8;j++)
            #pragma unroll
            for (int e=0;e<4;e++) acc[i][j][e] = 0.f;

    // ldmatrix base addresses (per-thread constant parts)
    // A x4: row = mt0 + (grp&1)*8 + l8, byte col = (grp>>1)*16
    // B x4: row = nb0 + (grp>>1)*8 + l8, byte col = (grp&1)*16
    const uint32_t aRowOff = (uint32_t)(((grp & 1)*8 + l8) * (SAELEM*2) + (grp >> 1)*16);
    const uint32_t bRowOff = (uint32_t)(((grp >> 1)*8 + l8) * (SAELEM*2) + (grp & 1)*16);

    for (int c = 0; c < DD/32; c++){
        int k0 = c*32;
        load_tile<false>(Abase, k0, sm.A, nullptr, tid);
        load_tile<true >(Bbase, k0, sm.B, sm.cn2, tid);
        __syncthreads();
        #pragma unroll
        for (int ks = 0; ks < 2; ks++){
            uint32_t kb = ks*32;
            uint32_t a[2][4];
            #pragma unroll
            for (int i = 0; i < 2; i++)
                ldsm_x4(a[i], sA + (wm*32 + i*16)*(SAELEM*2) + aRowOff + kb);
            uint32_t b[8][2];
            #pragma unroll
            for (int jj = 0; jj < 4; jj++){
                uint32_t r4[4];
                ldsm_x4(r4, sB + (wn*64 + jj*16)*(SAELEM*2) + bRowOff + kb);
                b[jj*2][0] = r4[0]; b[jj*2][1] = r4[1];
                b[jj*2+1][0] = r4[2]; b[jj*2+1][1] = r4[3];
            }
            #pragma unroll
            for (int i = 0; i < 2; i++)
                #pragma unroll
                for (int j = 0; j < 8; j++)
                    mma16816(acc[i][j], a[i], b[j]);
        }
        __syncthreads();
    }

    // epilogue: masked exp(-10*dist), per-row partial sums
    const int g = lane >> 2, tig = lane & 3;
    #pragma unroll
    for (int i = 0; i < 2; i++){
        int r0 = wm*32 + i*16 + g;
        int r1 = r0 + 8;
        float fn0 = g_fn2[p*BB + r0];
        float fn1 = g_fn2[p*BB + r1];
        float part0 = 0.f, part1 = 0.f;
        #pragma unroll
        for (int j = 0; j < 8; j++){
            int n = wn*64 + j*8 + tig*2;
            float mk0 = sm.mask[n],   mk1 = sm.mask[n+1];
            float cn0 = sm.cn2[n],    cn1 = sm.cn2[n+1];
            float d00 = fn0 + cn0 - 2.f*acc[i][j][0];
            float d01 = fn0 + cn1 - 2.f*acc[i][j][1];
            float d10 = fn1 + cn0 - 2.f*acc[i][j][2];
            float d11 = fn1 + cn1 - 2.f*acc[i][j][3];
            part0 += mk0*__expf(-SCALE_F*sqrtf(fmaxf(d00,1e-12f)))
                   + mk1*__expf(-SCALE_F*sqrtf(fmaxf(d01,1e-12f)));
            part1 += mk0*__expf(-SCALE_F*sqrtf(fmaxf(d10,1e-12f)))
                   + mk1*__expf(-SCALE_F*sqrtf(fmaxf(d11,1e-12f)));
        }
        part0 += __shfl_xor_sync(0xffffffffu, part0, 1);
        part0 += __shfl_xor_sync(0xffffffffu, part0, 2);
        part1 += __shfl_xor_sync(0xffffffffu, part1, 1);
        part1 += __shfl_xor_sync(0xffffffffu, part1, 2);
        if (tig == 0){
            sm.red[r0][wn] = part0;
            sm.red[r1][wn] = part1;
        }
    }
    __syncthreads();
    if (tid < BB)
        g_partial[((size_t)p*NT + tile)*BB + tid] = sm.red[tid][0] + sm.red[tid][1];
}

// ---------------- positive term ----------------------------------------------
__global__ void pos_kernel(const float* __restrict__ feature,
                           const float* __restrict__ centers,
                           const int* __restrict__ cross_indices){
    int p = blockIdx.x / BB, b = blockIdx.x % BB;
    int lane = threadIdx.x;
    const float* f = feature + (size_t)(p*BB+b)*DD;
    float fn2 = g_fn2[p*BB+b];
    float ssum = 0.f;
    for (int k = 0; k < KKc; k++){
        int idx = cross_indices[b*KKc + k];
        const float* c = centers + ((size_t)p*NN + idx)*DD;
        float dot = 0.f, sqv = 0.f;
        for (int d = lane; d < DD; d += 32){
            float cv = c[d];
            dot += f[d]*cv;
            sqv += cv*cv;
        }
        dot = warpSum(dot);
        sqv = warpSum(sqv);
        float pd2 = fn2 + sqv - 2.f*dot;
        float dist = sqrtf(fmaxf(pd2, 1e-12f));
        ssum += expf(-SCALE_F * dist);
    }
    if (lane == 0) g_x[p*BB+b] = logf(ssum);
}

// ---------------- pos_vid gather ---------------------------------------------
__global__ void posvid_kernel(const int* __restrict__ cross_indices,
                              const int* __restrict__ vid,
                              float* __restrict__ out, int out_size){
    int i = blockIdx.x*blockDim.x + threadIdx.x;
    if (i < BB*KKc && (3 + i) < out_size)
        out[3 + i] = (float)vid[cross_indices[i]];
}

// ---------------- final combine ----------------------------------------------
__global__ void final_kernel(float* __restrict__ out, int out_size){
    int b = threadIdx.x;
    float closs = 0.f;
    for (int p = 0; p < PP; p++){
        float ns = 0.f;
        for (int t = 0; t < NT; t++)
            ns += g_partial[((size_t)p*NT + t)*BB + b];
        float y = logf(ns);
        float v = y - g_x[p*BB + b];
        float s = blockSum128(v);
        float lp = s / (float)BB;
        if (isnan(lp)) lp = 0.f;
        closs += lp;
    }
    closs /= (float)PP;
    float aloss = 0.f;
    for (int p = 0; p < PP; p++){
        float nv = blockSum128((float)g_valid[p*BB + b]);
        float s1 = blockSum128(g_kl1[p*BB + b]);
        float s2 = blockSum128(g_kl2[p*BB + b]);
        float pp = 0.5f * (s1 + s2) / fmaxf(nv, 1.f);
        if (nv > 0.f) aloss += pp;
    }
    float klw = fmaxf(0.5f * (1.f - 1.f/60.f), 0.1f);
    float total = closs + klw * aloss;
    if (b == 0 && out_size >= 3){
        out[0] = total;
        out[1] = closs;
        out[2] = aloss;
    }
}

// ---------------- launch ------------------------------------------------------
extern "C" void kernel_launch(void* const* d_in, const int* in_sizes, int n_in,
                              void* d_out, int out_size){
    const float* feature       = (const float*)d_in[0];
    const float* text_feature  = (const float*)d_in[1];
    const float* centers       = (const float*)d_in[2];
    const int*   position      = (const int*)d_in[3];
    const int*   cross_indices = (const int*)d_in[4];
    const int*   vid           = (const int*)d_in[5];
    float* out = (float*)d_out;

    mask_init_kernel<<<NN/256, 256>>>();
    mask_scatter_kernel<<<(BB*KKc + BB + 255)/256, 256>>>(cross_indices, position);
    normalize_kernel<<<PP*BB, 128>>>(feature, text_feature);
    sim2_kernel<<<dim3(PP, 16), 256>>>(feature, text_feature);
    kl_kernel<<<PP*BB, 128>>>();
    neg_mma_kernel<<<dim3(NT, PP), 256>>>(feature, centers);
    pos_kernel<<<PP*BB, 32>>>(feature, centers, cross_indices);
    posvid_kernel<<<(BB*KKc + 255)/256, 256>>>(cross_indices, vid, out, out_size);
    final_kernel<<<1, 128>>>(out, out_size);
}

// round 4
// speedup vs baseline: 2.1440x; 1.1896x over previous
#include <cuda_runtime.h>
#include <cuda_bf16.h>
#include <cstdint>
#include <math.h>

#define PP 4
#define BB 128
#define DD 512
#define NN 32768
#define KKc 10
#define NT 256          // NN / 128 tiles
#define NEG_INF_F (-1e30f)
#define SIM_TH_F 0.7f
#define SCALE_F 10.0f

// ---------------- scratch (device globals) -----------------------------------
__device__ float g_invI[PP*BB];
__device__ float g_invT[PP*BB];
__device__ float g_fn2[PP*BB];
__device__ float g_img_sim[PP*BB*BB];
__device__ float g_txt_sim[PP*BB*BB];
__device__ int   g_valid[PP*BB];
__device__ float g_kl1[PP*BB];
__device__ float g_kl2[PP*BB];
__device__ float g_x[PP*BB];
__device__ float g_partial[PP*NT*BB];
__device__ unsigned char g_negmask[NN];

// ---------------- warp helpers ------------------------------------------------
__device__ __forceinline__ float warpSum(float v){
    #pragma unroll
    for (int o=16;o;o>>=1) v += __shfl_xor_sync(0xffffffffu, v, o);
    return v;
}
__device__ __forceinline__ float warpMax(float v){
    #pragma unroll
    for (int o=16;o;o>>=1) v = fmaxf(v, __shfl_xor_sync(0xffffffffu, v, o));
    return v;
}
__device__ float blockSum128(float v){
    __shared__ float sh[4];
    int w = threadIdx.x>>5, l = threadIdx.x&31;
    v = warpSum(v);
    __syncthreads();
    if (l==0) sh[w] = v;
    __syncthreads();
    return sh[0]+sh[1]+sh[2]+sh[3];
}
__device__ float blockMax128(float v){
    __shared__ float sh[4];
    int w = threadIdx.x>>5, l = threadIdx.x&31;
    v = warpMax(v);
    __syncthreads();
    if (l==0) sh[w] = v;
    __syncthreads();
    return fmaxf(fmaxf(sh[0],sh[1]), fmaxf(sh[2],sh[3]));
}
__device__ __forceinline__ uint32_t smem_u32(const void* p){
    uint32_t a;
    asm("{ .reg .u64 t; cvta.to.shared.u64 t, %1; cvt.u32.u64 %0, t; }" : "=r"(a) : "l"(p));
    return a;
}
__device__ __forceinline__ void ldsm_x4(uint32_t* r, uint32_t addr){
    asm volatile("ldmatrix.sync.aligned.m8n8.x4.shared.b16 {%0,%1,%2,%3}, [%4];"
                 : "=r"(r[0]), "=r"(r[1]), "=r"(r[2]), "=r"(r[3]) : "r"(addr));
}
__device__ __forceinline__ void mma16816(float* c, const uint32_t* a, const uint32_t* b){
    asm volatile("mma.sync.aligned.m16n8k16.row.col.f32.bf16.bf16.f32 "
                 "{%0,%1,%2,%3}, {%4,%5,%6,%7}, {%8,%9}, {%0,%1,%2,%3};"
                 : "+f"(c[0]), "+f"(c[1]), "+f"(c[2]), "+f"(c[3])
                 : "r"(a[0]), "r"(a[1]), "r"(a[2]), "r"(a[3]), "r"(b[0]), "r"(b[1]));
}

// ---------------- normalize (+ negmask init) ---------------------------------
// grid = PP*BB blocks, 128 threads
__global__ void normalize_kernel(const float* __restrict__ feature,
                                 const float* __restrict__ text_feature){
    int p = blockIdx.x / BB, b = blockIdx.x % BB;
    int tid = threadIdx.x;
    // fused negmask init: 512 blocks * 128 threads = 65536 >= NN
    int gi = blockIdx.x*128 + tid;
    if (gi < NN) g_negmask[gi] = 1;

    const float* f = feature + (size_t)(p*BB + b)*DD;
    const float* t = text_feature + (size_t)(b*PP + p)*DD;
    float sf = 0.f, st = 0.f;
    for (int d = tid; d < DD; d += 128){ float v=f[d]; sf += v*v; float w=t[d]; st += w*w; }
    __shared__ float sh[8];
    int w = tid>>5, l = tid&31;
    sf = warpSum(sf); st = warpSum(st);
    if (l==0){ sh[w]=sf; sh[4+w]=st; }
    __syncthreads();
    if (tid == 0){
        float fn2 = sh[0]+sh[1]+sh[2]+sh[3];
        float tn2 = sh[4]+sh[5]+sh[6]+sh[7];
        g_fn2[p*BB+b]  = fn2;
        g_invI[p*BB+b] = 1.f / fmaxf(sqrtf(fn2), 1e-12f);
        g_invT[p*BB+b] = 1.f / fmaxf(sqrtf(tn2), 1e-12f);
    }
}

// ---------------- sims: tiled fp32 GEMM --------------------------------------
// grid (PP, 4 row-tiles of 32, 2 matrices), 256 threads (16x16), 2x8 microtile
#define SIMK 32
__global__ __launch_bounds__(256) void sim3_kernel(const float* __restrict__ feature,
                                                   const float* __restrict__ text){
    const int p = blockIdx.x, rt = blockIdx.y, mat = blockIdx.z;
    const int tid = threadIdx.x;
    const int tx = tid & 15, ty = tid >> 4;
    __shared__ float sA[SIMK][36];    // [k][row 0..31]
    __shared__ float sB[SIMK][132];   // [k][col 0..127]
    const float* inv = (mat == 0) ? g_invI : g_invT;
    const int r0 = rt*32;

    // loader indices (fixed per thread)
    const int ar = tid >> 3, aq = tid & 7;          // A: row 0..31, k-quad 0..7
    const float invA = inv[p*BB + r0 + ar];
    const float* aPtr = (mat == 0)
        ? feature + (size_t)(p*BB + r0 + ar)*DD + aq*4
        : text    + (size_t)((r0 + ar)*PP + p)*DD + aq*4;
    float invB[4];
    const float* bPtr[4];
    #pragma unroll
    for (int it = 0; it < 4; it++){
        int idx = it*256 + tid;
        int br = idx >> 3, bq = idx & 7;
        invB[it] = inv[p*BB + br];
        bPtr[it] = (mat == 0)
            ? feature + (size_t)(p*BB + br)*DD + bq*4
            : text    + (size_t)(br*PP + p)*DD + bq*4;
    }

    float acc[2][8];
    #pragma unroll
    for (int i=0;i<2;i++)
        #pragma unroll
        for (int j=0;j<8;j++) acc[i][j] = 0.f;

    for (int k0 = 0; k0 < DD; k0 += SIMK){
        // load + transpose into smem, scaled by inv norms
        {
            float4 v = *(const float4*)(aPtr + k0);
            sA[aq*4+0][ar] = v.x*invA; sA[aq*4+1][ar] = v.y*invA;
            sA[aq*4+2][ar] = v.z*invA; sA[aq*4+3][ar] = v.w*invA;
        }
        #pragma unroll
        for (int it = 0; it < 4; it++){
            int idx = it*256 + tid;
            int br = idx >> 3, bq = idx & 7;
            float4 v = *(const float4*)(bPtr[it] + k0);
            float iv = invB[it];
            sB[bq*4+0][br] = v.x*iv; sB[bq*4+1][br] = v.y*iv;
            sB[bq*4+2][br] = v.z*iv; sB[bq*4+3][br] = v.w*iv;
        }
        __syncthreads();
        #pragma unroll
        for (int k = 0; k < SIMK; k++){
            float a0 = sA[k][ty], a1 = sA[k][ty+16];
            float4 b0 = *(const float4*)&sB[k][tx*8];
            float4 b1 = *(const float4*)&sB[k][tx*8+4];
            float bb[8] = {b0.x,b0.y,b0.z,b0.w,b1.x,b1.y,b1.z,b1.w};
            #pragma unroll
            for (int j = 0; j < 8; j++){
                acc[0][j] += a0*bb[j];
                acc[1][j] += a1*bb[j];
            }
        }
        __syncthreads();
    }

    float* osim = (mat == 0) ? g_img_sim : g_txt_sim;
    #pragma unroll
    for (int i = 0; i < 2; i++){
        int row = r0 + ty + i*16;
        float4 o0, o1;
        o0.x = acc[i][0]*2.f; o0.y = acc[i][1]*2.f; o0.z = acc[i][2]*2.f; o0.w = acc[i][3]*2.f;
        o1.x = acc[i][4]*2.f; o1.y = acc[i][5]*2.f; o1.z = acc[i][6]*2.f; o1.w = acc[i][7]*2.f;
        float* dst = osim + ((size_t)(p*BB + row))*BB + tx*8;
        *(float4*)dst = o0;
        *(float4*)(dst+4) = o1;
    }
}

// ---------------- valid flags (+ negmask scatter) -----------------------------
// grid = PP*BB blocks, 128 threads
__global__ void valid_kernel(const int* __restrict__ cross_indices,
                             const int* __restrict__ position){
    int row = blockIdx.x;     // p*BB + b
    int c = threadIdx.x;
    float is = g_img_sim[(size_t)row*BB + c];
    float ts = g_txt_sim[(size_t)row*BB + c];
    int v = __syncthreads_or((is > SIM_TH_F) && (ts > SIM_TH_F));
    if (c == 0) g_valid[row] = v;
    if (row < BB){            // fused scatter (runs once: blocks with p==0)
        if (c < KKc)       g_negmask[cross_indices[row*KKc + c]] = 0;
        else if (c == KKc) g_negmask[position[row]] = 0;
    }
}

// ---------------- masked softmax + KL per row --------------------------------
__global__ void kl_kernel(){
    int p = blockIdx.x / BB, b = blockIdx.x % BB;
    int c = threadIdx.x;
    float is = g_img_sim[((size_t)(p*BB+b))*BB + c];
    float ts = g_txt_sim[((size_t)(p*BB+b))*BB + c];
    int colm = g_valid[p*BB + c];
    float il = colm ? is : NEG_INF_F;
    float tl = colm ? ts : NEG_INF_F;
    float mi = blockMax128(il);
    float sumi = blockSum128(expf(il - mi));
    float lsei = mi + logf(sumi);
    float mt = blockMax128(tl);
    float sumt = blockSum128(expf(tl - mt));
    float lset = mt + logf(sumt);
    float img_logp = il - lsei;
    float txt_logp = tl - lset;
    float k1 = colm ? expf(txt_logp) * (txt_logp - img_logp) : 0.f;
    float k2 = colm ? expf(img_logp) * (img_logp - txt_logp) : 0.f;
    float s1 = blockSum128(k1);
    float s2 = blockSum128(k2);
    if (c == 0){
        int rv = g_valid[p*BB + b];
        g_kl1[p*BB+b] = rv ? s1 : 0.f;
        g_kl2[p*BB+b] = rv ? s2 : 0.f;
    }
}

// ---------------- neg distances: pipelined bf16 HMMA GEMM --------------------
// grid (NT, P), 256 threads = 8 warps 4(M)x2(N). M=128, N=128, K=512, 16 chunks
// of K=32, double-buffered smem, register prefetch, 1 sync per chunk.
#define SAELEM 40    // bf16 per smem row (32 + 8 pad; 80B stride conflict-free)

struct NegSmem {
    __nv_bfloat16 A[2][BB*SAELEM];
    __nv_bfloat16 B[2][BB*SAELEM];
    float cn2[BB];
    float mask[BB];
    float red[BB][2];
};

__device__ __forceinline__ void load_regs(const float* __restrict__ gbase, int k0,
                                          int tid, float4* r){
    #pragma unroll
    for (int it = 0; it < 4; it++){
        int idx = it*256 + tid;
        int rr = idx >> 3, q = idx & 7;
        r[it] = *(const float4*)(gbase + (size_t)rr*DD + k0 + q*4);
    }
}
__device__ __forceinline__ void store_regs(__nv_bfloat16* sdst, int tid, const float4* r){
    #pragma unroll
    for (int it = 0; it < 4; it++){
        int idx = it*256 + tid;
        int rr = idx >> 3, q = idx & 7;
        __nv_bfloat162 h0 = __floats2bfloat162_rn(r[it].x, r[it].y);
        __nv_bfloat162 h1 = __floats2bfloat162_rn(r[it].z, r[it].w);
        uint2 pk;
        pk.x = *reinterpret_cast<const uint32_t*>(&h0);
        pk.y = *reinterpret_cast<const uint32_t*>(&h1);
        *reinterpret_cast<uint2*>((char*)sdst + rr*(SAELEM*2) + q*8) = pk;
    }
}

__global__ __launch_bounds__(256) void neg_mma_kernel(const float* __restrict__ feature,
                                                      const float* __restrict__ centers){
    __shared__ NegSmem sm;
    const int p = blockIdx.y;
    const int tile = blockIdx.x;
    const int n0g = tile * 128;
    const int tid = threadIdx.x;
    const int wid = tid >> 5, lane = tid & 31;
    const int wm = wid >> 1, wn = wid & 1;
    const int l8 = lane & 7, grp = lane >> 3;

    if (tid < BB) sm.mask[tid] = g_negmask[n0g + tid] ? 1.f : 0.f;

    const float* Abase = feature + (size_t)p*BB*DD;
    const float* Bbase = centers + ((size_t)p*NN + n0g)*DD;
    const uint32_t sAu[2] = { smem_u32(sm.A[0]), smem_u32(sm.A[1]) };
    const uint32_t sBu[2] = { smem_u32(sm.B[0]), smem_u32(sm.B[1]) };

    float acc[2][8][4];
    #pragma unroll
    for (int i=0;i<2;i++)
        #pragma unroll
        for (int j=0;j<8;j++)
            #pragma unroll
            for (int e=0;e<4;e++) acc[i][j][e] = 0.f;

    const uint32_t aRowOff = (uint32_t)(((grp & 1)*8 + l8) * (SAELEM*2) + (grp >> 1)*16);
    const uint32_t bRowOff = (uint32_t)(((grp >> 1)*8 + l8) * (SAELEM*2) + (grp & 1)*16);

    float4 rA[4], rB[4];
    float sqAcc[4] = {0.f, 0.f, 0.f, 0.f};
    load_regs(Abase, 0, tid, rA);
    load_regs(Bbase, 0, tid, rB);

    for (int c = 0; c < DD/32; c++){
        const int buf = c & 1;
        store_regs(sm.A[buf], tid, rA);
        store_regs(sm.B[buf], tid, rB);
        #pragma unroll
        for (int it = 0; it < 4; it++)
            sqAcc[it] += rB[it].x*rB[it].x + rB[it].y*rB[it].y
                       + rB[it].z*rB[it].z + rB[it].w*rB[it].w;
        if (c < DD/32 - 1){
            load_regs(Abase, (c+1)*32, tid, rA);
            load_regs(Bbase, (c+1)*32, tid, rB);
        }
        __syncthreads();
        #pragma unroll
        for (int ks = 0; ks < 2; ks++){
            uint32_t kb = ks*32;
            uint32_t a[2][4];
            #pragma unroll
            for (int i = 0; i < 2; i++)
                ldsm_x4(a[i], sAu[buf] + (wm*32 + i*16)*(SAELEM*2) + aRowOff + kb);
            uint32_t b[8][2];
            #pragma unroll
            for (int jj = 0; jj < 4; jj++){
                uint32_t r4[4];
                ldsm_x4(r4, sBu[buf] + (wn*64 + jj*16)*(SAELEM*2) + bRowOff + kb);
                b[jj*2][0] = r4[0]; b[jj*2][1] = r4[1];
                b[jj*2+1][0] = r4[2]; b[jj*2+1][1] = r4[3];
            }
            #pragma unroll
            for (int i = 0; i < 2; i++)
                #pragma unroll
                for (int j = 0; j < 8; j++)
                    mma16816(acc[i][j], a[i], b[j]);
        }
    }

    // write cn2 (register-accumulated squared norms of B rows)
    #pragma unroll
    for (int it = 0; it < 4; it++){
        float sq = sqAcc[it];
        sq += __shfl_xor_sync(0xffffffffu, sq, 1);
        sq += __shfl_xor_sync(0xffffffffu, sq, 2);
        sq += __shfl_xor_sync(0xffffffffu, sq, 4);
        if ((lane & 7) == 0) sm.cn2[(it*256 + tid) >> 3] = sq;
    }
    __syncthreads();

    // epilogue: masked exp(-10*dist), per-row partial sums
    const int g = lane >> 2, tig = lane & 3;
    #pragma unroll
    for (int i = 0; i < 2; i++){
        int r0 = wm*32 + i*16 + g;
        int r1 = r0 + 8;
        float fn0 = g_fn2[p*BB + r0];
        float fn1 = g_fn2[p*BB + r1];
        float part0 = 0.f, part1 = 0.f;
        #pragma unroll
        for (int j = 0; j < 8; j++){
            int n = wn*64 + j*8 + tig*2;
            float mk0 = sm.mask[n],   mk1 = sm.mask[n+1];
            float cn0 = sm.cn2[n],    cn1 = sm.cn2[n+1];
            float d00 = fn0 + cn0 - 2.f*acc[i][j][0];
            float d01 = fn0 + cn1 - 2.f*acc[i][j][1];
            float d10 = fn1 + cn0 - 2.f*acc[i][j][2];
            float d11 = fn1 + cn1 - 2.f*acc[i][j][3];
            part0 += mk0*__expf(-SCALE_F*sqrtf(fmaxf(d00,1e-12f)))
                   + mk1*__expf(-SCALE_F*sqrtf(fmaxf(d01,1e-12f)));
            part1 += mk0*__expf(-SCALE_F*sqrtf(fmaxf(d10,1e-12f)))
                   + mk1*__expf(-SCALE_F*sqrtf(fmaxf(d11,1e-12f)));
        }
        part0 += __shfl_xor_sync(0xffffffffu, part0, 1);
        part0 += __shfl_xor_sync(0xffffffffu, part0, 2);
        part1 += __shfl_xor_sync(0xffffffffu, part1, 1);
        part1 += __shfl_xor_sync(0xffffffffu, part1, 2);
        if (tig == 0){
            sm.red[r0][wn] = part0;
            sm.red[r1][wn] = part1;
        }
    }
    __syncthreads();
    if (tid < BB)
        g_partial[((size_t)p*NT + tile)*BB + tid] = sm.red[tid][0] + sm.red[tid][1];
}

// ---------------- positive term ----------------------------------------------
__global__ void pos_kernel(const float* __restrict__ feature,
                           const float* __restrict__ centers,
                           const int* __restrict__ cross_indices){
    int p = blockIdx.x / BB, b = blockIdx.x % BB;
    int lane = threadIdx.x;
    const float* f = feature + (size_t)(p*BB+b)*DD;
    float fn2 = g_fn2[p*BB+b];
    float ssum = 0.f;
    for (int k = 0; k < KKc; k++){
        int idx = cross_indices[b*KKc + k];
        const float* c = centers + ((size_t)p*NN + idx)*DD;
        float dot = 0.f, sqv = 0.f;
        for (int d = lane; d < DD; d += 32){
            float cv = c[d];
            dot += f[d]*cv;
            sqv += cv*cv;
        }
        dot = warpSum(dot);
        sqv = warpSum(sqv);
        float pd2 = fn2 + sqv - 2.f*dot;
        float dist = sqrtf(fmaxf(pd2, 1e-12f));
        ssum += expf(-SCALE_F * dist);
    }
    if (lane == 0) g_x[p*BB+b] = logf(ssum);
}

// ---------------- pos_vid gather ---------------------------------------------
__global__ void posvid_kernel(const int* __restrict__ cross_indices,
                              const int* __restrict__ vid,
                              float* __restrict__ out, int out_size){
    int i = blockIdx.x*blockDim.x + threadIdx.x;
    if (i < BB*KKc && (3 + i) < out_size)
        out[3 + i] = (float)vid[cross_indices[i]];
}

// ---------------- final combine ----------------------------------------------
__global__ void final_kernel(float* __restrict__ out, int out_size){
    int b = threadIdx.x;
    float closs = 0.f;
    for (int p = 0; p < PP; p++){
        float ns = 0.f;
        for (int t = 0; t < NT; t++)
            ns += g_partial[((size_t)p*NT + t)*BB + b];
        float y = logf(ns);
        float v = y - g_x[p*BB + b];
        float s = blockSum128(v);
        float lp = s / (float)BB;
        if (isnan(lp)) lp = 0.f;
        closs += lp;
    }
    closs /= (float)PP;
    float aloss = 0.f;
    for (int p = 0; p < PP; p++){
        float nv = blockSum128((float)g_valid[p*BB + b]);
        float s1 = blockSum128(g_kl1[p*BB + b]);
        float s2 = blockSum128(g_kl2[p*BB + b]);
        float pp = 0.5f * (s1 + s2) / fmaxf(nv, 1.f);
        if (nv > 0.f) aloss += pp;
    }
    float klw = fmaxf(0.5f * (1.f - 1.f/60.f), 0.1f);
    float total = closs + klw * aloss;
    if (b == 0 && out_size >= 3){
        out[0] = total;
        out[1] = closs;
        out[2] = aloss;
    }
}

// ---------------- launch ------------------------------------------------------
extern "C" void kernel_launch(void* const* d_in, const int* in_sizes, int n_in,
                              void* d_out, int out_size){
    const float* feature       = (const float*)d_in[0];
    const float* text_feature  = (const float*)d_in[1];
    const float* centers       = (const float*)d_in[2];
    const int*   position      = (const int*)d_in[3];
    const int*   cross_indices = (const int*)d_in[4];
    const int*   vid           = (const int*)d_in[5];
    float* out = (float*)d_out;

    normalize_kernel<<<PP*BB, 128>>>(feature, text_feature);       // + mask init
    sim3_kernel<<<dim3(PP, 4, 2), 256>>>(feature, text_feature);
    valid_kernel<<<PP*BB, 128>>>(cross_indices, position);         // + mask scatter
    kl_kernel<<<PP*BB, 128>>>();
    neg_mma_kernel<<<dim3(NT, PP), 256>>>(feature, centers);
    pos_kernel<<<PP*BB, 32>>>(feature, centers, cross_indices);
    posvid_kernel<<<(BB*KKc + 255)/256, 256>>>(cross_indices, vid, out, out_size);
    final_kernel<<<1, 128>>>(out, out_size);
}

// round 5
// speedup vs baseline: 2.3367x; 1.0899x over previous
#include <cuda_runtime.h>
#include <cuda_bf16.h>
#include <cstdint>
#include <math.h>

#define PP 4
#define BB 128
#define DD 512
#define NN 32768
#define KKc 10
#define NT 256          // NN / 128 tiles
#define NEG_INF_F (-1e30f)
#define SIM_TH_F 0.7f
#define SCALE_F 10.0f

// ---------------- scratch (device globals) -----------------------------------
__device__ float g_invI[PP*BB];
__device__ float g_invT[PP*BB];
__device__ float g_fn2[PP*BB];
__device__ float g_img_sim[PP*BB*BB];
__device__ float g_txt_sim[PP*BB*BB];
__device__ int   g_valid[PP*BB];
__device__ float g_kl1[PP*BB];
__device__ float g_kl2[PP*BB];
__device__ float g_x[PP*BB];
__device__ float g_partial[PP*NT*BB];
__device__ unsigned char g_negmask[NN];

// ---------------- warp helpers ------------------------------------------------
__device__ __forceinline__ float warpSum(float v){
    #pragma unroll
    for (int o=16;o;o>>=1) v += __shfl_xor_sync(0xffffffffu, v, o);
    return v;
}
__device__ __forceinline__ float warpMax(float v){
    #pragma unroll
    for (int o=16;o;o>>=1) v = fmaxf(v, __shfl_xor_sync(0xffffffffu, v, o));
    return v;
}
__device__ float blockSum128(float v){
    __shared__ float sh[4];
    int w = threadIdx.x>>5, l = threadIdx.x&31;
    v = warpSum(v);
    __syncthreads();
    if (l==0) sh[w] = v;
    __syncthreads();
    return sh[0]+sh[1]+sh[2]+sh[3];
}
__device__ float blockMax128(float v){
    __shared__ float sh[4];
    int w = threadIdx.x>>5, l = threadIdx.x&31;
    v = warpMax(v);
    __syncthreads();
    if (l==0) sh[w] = v;
    __syncthreads();
    return fmaxf(fmaxf(sh[0],sh[1]), fmaxf(sh[2],sh[3]));
}
__device__ __forceinline__ uint32_t smem_u32(const void* p){
    uint32_t a;
    asm("{ .reg .u64 t; cvta.to.shared.u64 t, %1; cvt.u32.u64 %0, t; }" : "=r"(a) : "l"(p));
    return a;
}
__device__ __forceinline__ void ldsm_x4(uint32_t* r, uint32_t addr){
    asm volatile("ldmatrix.sync.aligned.m8n8.x4.shared.b16 {%0,%1,%2,%3}, [%4];"
                 : "=r"(r[0]), "=r"(r[1]), "=r"(r[2]), "=r"(r[3]) : "r"(addr));
}
__device__ __forceinline__ void mma16816(float* c, const uint32_t* a, const uint32_t* b){
    asm volatile("mma.sync.aligned.m16n8k16.row.col.f32.bf16.bf16.f32 "
                 "{%0,%1,%2,%3}, {%4,%5,%6,%7}, {%8,%9}, {%0,%1,%2,%3};"
                 : "+f"(c[0]), "+f"(c[1]), "+f"(c[2]), "+f"(c[3])
                 : "r"(a[0]), "r"(a[1]), "r"(a[2]), "r"(a[3]), "r"(b[0]), "r"(b[1]));
}
__device__ __forceinline__ void cpasync16(uint32_t dst, const void* src){
    asm volatile("cp.async.cg.shared.global [%0], [%1], 16;" :: "r"(dst), "l"(src));
}
#define CP_COMMIT() asm volatile("cp.async.commit_group;" ::: "memory")
#define CP_WAIT1()  asm volatile("cp.async.wait_group 1;" ::: "memory")

// ---------------- normalize (+ negmask init) ---------------------------------
__global__ void normalize_kernel(const float* __restrict__ feature,
                                 const float* __restrict__ text_feature){
    int p = blockIdx.x / BB, b = blockIdx.x % BB;
    int tid = threadIdx.x;
    int gi = blockIdx.x*128 + tid;
    if (gi < NN) g_negmask[gi] = 1;

    const float* f = feature + (size_t)(p*BB + b)*DD;
    const float* t = text_feature + (size_t)(b*PP + p)*DD;
    float sf = 0.f, st = 0.f;
    for (int d = tid; d < DD; d += 128){ float v=f[d]; sf += v*v; float w=t[d]; st += w*w; }
    __shared__ float sh[8];
    int w = tid>>5, l = tid&31;
    sf = warpSum(sf); st = warpSum(st);
    if (l==0){ sh[w]=sf; sh[4+w]=st; }
    __syncthreads();
    if (tid == 0){
        float fn2 = sh[0]+sh[1]+sh[2]+sh[3];
        float tn2 = sh[4]+sh[5]+sh[6]+sh[7];
        g_fn2[p*BB+b]  = fn2;
        g_invI[p*BB+b] = 1.f / fmaxf(sqrtf(fn2), 1e-12f);
        g_invT[p*BB+b] = 1.f / fmaxf(sqrtf(tn2), 1e-12f);
    }
}

// ---------------- sims: tiled fp32 GEMM --------------------------------------
#define SIMK 32
__global__ __launch_bounds__(256) void sim3_kernel(const float* __restrict__ feature,
                                                   const float* __restrict__ text){
    const int p = blockIdx.x, rt = blockIdx.y, mat = blockIdx.z;
    const int tid = threadIdx.x;
    const int tx = tid & 15, ty = tid >> 4;
    __shared__ float sA[SIMK][36];
    __shared__ float sB[SIMK][132];
    const float* inv = (mat == 0) ? g_invI : g_invT;
    const int r0 = rt*32;

    const int ar = tid >> 3, aq = tid & 7;
    const float invA = inv[p*BB + r0 + ar];
    const float* aPtr = (mat == 0)
        ? feature + (size_t)(p*BB + r0 + ar)*DD + aq*4
        : text    + (size_t)((r0 + ar)*PP + p)*DD + aq*4;
    float invB[4];
    const float* bPtr[4];
    #pragma unroll
    for (int it = 0; it < 4; it++){
        int idx = it*256 + tid;
        int br = idx >> 3, bq = idx & 7;
        invB[it] = inv[p*BB + br];
        bPtr[it] = (mat == 0)
            ? feature + (size_t)(p*BB + br)*DD + bq*4
            : text    + (size_t)(br*PP + p)*DD + bq*4;
    }

    float acc[2][8];
    #pragma unroll
    for (int i=0;i<2;i++)
        #pragma unroll
        for (int j=0;j<8;j++) acc[i][j] = 0.f;

    for (int k0 = 0; k0 < DD; k0 += SIMK){
        {
            float4 v = *(const float4*)(aPtr + k0);
            sA[aq*4+0][ar] = v.x*invA; sA[aq*4+1][ar] = v.y*invA;
            sA[aq*4+2][ar] = v.z*invA; sA[aq*4+3][ar] = v.w*invA;
        }
        #pragma unroll
        for (int it = 0; it < 4; it++){
            int idx = it*256 + tid;
            int br = idx >> 3, bq = idx & 7;
            float4 v = *(const float4*)(bPtr[it] + k0);
            float iv = invB[it];
            sB[bq*4+0][br] = v.x*iv; sB[bq*4+1][br] = v.y*iv;
            sB[bq*4+2][br] = v.z*iv; sB[bq*4+3][br] = v.w*iv;
        }
        __syncthreads();
        #pragma unroll
        for (int k = 0; k < SIMK; k++){
            float a0 = sA[k][ty], a1 = sA[k][ty+16];
            float4 b0 = *(const float4*)&sB[k][tx*8];
            float4 b1 = *(const float4*)&sB[k][tx*8+4];
            float bb[8] = {b0.x,b0.y,b0.z,b0.w,b1.x,b1.y,b1.z,b1.w};
            #pragma unroll
            for (int j = 0; j < 8; j++){
                acc[0][j] += a0*bb[j];
                acc[1][j] += a1*bb[j];
            }
        }
        __syncthreads();
    }

    float* osim = (mat == 0) ? g_img_sim : g_txt_sim;
    #pragma unroll
    for (int i = 0; i < 2; i++){
        int row = r0 + ty + i*16;
        float4 o0, o1;
        o0.x = acc[i][0]*2.f; o0.y = acc[i][1]*2.f; o0.z = acc[i][2]*2.f; o0.w = acc[i][3]*2.f;
        o1.x = acc[i][4]*2.f; o1.y = acc[i][5]*2.f; o1.z = acc[i][6]*2.f; o1.w = acc[i][7]*2.f;
        float* dst = osim + ((size_t)(p*BB + row))*BB + tx*8;
        *(float4*)dst = o0;
        *(float4*)(dst+4) = o1;
    }
}

// ---------------- valid flags (+ negmask scatter) -----------------------------
__global__ void valid_kernel(const int* __restrict__ cross_indices,
                             const int* __restrict__ position){
    int row = blockIdx.x;
    int c = threadIdx.x;
    float is = g_img_sim[(size_t)row*BB + c];
    float ts = g_txt_sim[(size_t)row*BB + c];
    int v = __syncthreads_or((is > SIM_TH_F) && (ts > SIM_TH_F));
    if (c == 0) g_valid[row] = v;
    if (row < BB){
        if (c < KKc)       g_negmask[cross_indices[row*KKc + c]] = 0;
        else if (c == KKc) g_negmask[position[row]] = 0;
    }
}

// ---------------- masked softmax + KL per row --------------------------------
__global__ void kl_kernel(){
    int p = blockIdx.x / BB, b = blockIdx.x % BB;
    int c = threadIdx.x;
    float is = g_img_sim[((size_t)(p*BB+b))*BB + c];
    float ts = g_txt_sim[((size_t)(p*BB+b))*BB + c];
    int colm = g_valid[p*BB + c];
    float il = colm ? is : NEG_INF_F;
    float tl = colm ? ts : NEG_INF_F;
    float mi = blockMax128(il);
    float sumi = blockSum128(expf(il - mi));
    float lsei = mi + logf(sumi);
    float mt = blockMax128(tl);
    float sumt = blockSum128(expf(tl - mt));
    float lset = mt + logf(sumt);
    float img_logp = il - lsei;
    float txt_logp = tl - lset;
    float k1 = colm ? expf(txt_logp) * (txt_logp - img_logp) : 0.f;
    float k2 = colm ? expf(img_logp) * (img_logp - txt_logp) : 0.f;
    float s1 = blockSum128(k1);
    float s2 = blockSum128(k2);
    if (c == 0){
        int rv = g_valid[p*BB + b];
        g_kl1[p*BB+b] = rv ? s1 : 0.f;
        g_kl2[p*BB+b] = rv ? s2 : 0.f;
    }
}

// ---------------- neg distances: cp.async pipelined bf16 HMMA GEMM -----------
// grid (NT, P), 256 thr = 8 warps 4(M)x2(N). M=128, N=128, K=512 in 16 chunks.
// cp.async fp32 -> raw smem (2 stages), smem convert -> bf16 (1 buffer), mma.
#define SAELEM 40            // bf16 per row (32+8 pad), 80B stride
#define RAWSTRIDE 144        // bytes per raw row (128 + 16 pad)
#define RAWSZ (BB*RAWSTRIDE) // 18432 B per raw stage
#define OFF_RAWA 0
#define OFF_RAWB (2*RAWSZ)
#define OFF_BA   (4*RAWSZ)
#define OFF_BB_  (4*RAWSZ + BB*SAELEM*2)
#define OFF_CN2  (4*RAWSZ + 2*BB*SAELEM*2)
#define OFF_MASK (OFF_CN2 + 512)
#define OFF_RED  (OFF_MASK + 512)
#define NEG_SMEM (OFF_RED + 1024)

__device__ __forceinline__ void issue_chunk(const float* __restrict__ Abase,
                                            const float* __restrict__ Bbase,
                                            uint32_t rawA, uint32_t rawB,
                                            int k0, int tid){
    #pragma unroll
    for (int j = 0; j < 4; j++){
        int idx = j*256 + tid;
        int r = idx >> 3, q = idx & 7;
        cpasync16(rawA + r*RAWSTRIDE + q*16, Abase + (size_t)r*DD + k0 + q*4);
    }
    #pragma unroll
    for (int j = 0; j < 4; j++){
        int idx = j*256 + tid;
        int r = idx >> 3, q = idx & 7;
        cpasync16(rawB + r*RAWSTRIDE + q*16, Bbase + (size_t)r*DD + k0 + q*4);
    }
}

__global__ __launch_bounds__(256, 2) void neg_mma_kernel(const float* __restrict__ feature,
                                                         const float* __restrict__ centers){
    extern __shared__ __align__(16) char dsm[];
    const int p = blockIdx.y;
    const int tile = blockIdx.x;
    const int n0g = tile * 128;
    const int tid = threadIdx.x;
    const int wid = tid >> 5, lane = tid & 31;
    const int wm = wid >> 1, wn = wid & 1;
    const int l8 = lane & 7, grp = lane >> 3;

    float* s_cn2  = (float*)(dsm + OFF_CN2);
    float* s_mask = (float*)(dsm + OFF_MASK);
    float* s_red  = (float*)(dsm + OFF_RED);
    if (tid < BB) s_mask[tid] = g_negmask[n0g + tid] ? 1.f : 0.f;

    const float* Abase = feature + (size_t)p*BB*DD;
    const float* Bbase = centers + ((size_t)p*NN + n0g)*DD;
    const uint32_t base = smem_u32(dsm);
    const uint32_t rawA[2] = { base + OFF_RAWA, base + OFF_RAWA + RAWSZ };
    const uint32_t rawB[2] = { base + OFF_RAWB, base + OFF_RAWB + RAWSZ };
    const uint32_t bAu = base + OFF_BA;
    const uint32_t bBu = base + OFF_BB_;

    float acc[2][8][4];
    #pragma unroll
    for (int i=0;i<2;i++)
        #pragma unroll
        for (int j=0;j<8;j++)
            #pragma unroll
            for (int e=0;e<4;e++) acc[i][j][e] = 0.f;

    const uint32_t aRowOff = (uint32_t)(((grp & 1)*8 + l8) * (SAELEM*2) + (grp >> 1)*16);
    const uint32_t bRowOff = (uint32_t)(((grp >> 1)*8 + l8) * (SAELEM*2) + (grp & 1)*16);

    // convert-phase thread mapping: row r0, half h (16 floats)
    const int r0c = tid >> 1, hc = tid & 1;
    float sqAcc = 0.f;

    // prologue: stage chunks 0 and 1
    issue_chunk(Abase, Bbase, rawA[0], rawB[0], 0, tid);
    CP_COMMIT();
    issue_chunk(Abase, Bbase, rawA[1], rawB[1], 32, tid);
    CP_COMMIT();

    for (int c = 0; c < DD/32; c++){
        const int st = c & 1;
        CP_WAIT1();           // chunk c resident
        __syncthreads();
        // convert raw fp32 -> bf16 (A), accumulate cn2 from B
        {
            const char* srcA = (const char*)dsm + OFF_RAWA + st*RAWSZ + r0c*RAWSTRIDE + hc*64;
            const char* srcB = (const char*)dsm + OFF_RAWB + st*RAWSZ + r0c*RAWSTRIDE + hc*64;
            uint32_t hA[8], hB[8];
            #pragma unroll
            for (int i = 0; i < 4; i++){
                float4 va = *(const float4*)(srcA + i*16);
                __nv_bfloat162 a0 = __floats2bfloat162_rn(va.x, va.y);
                __nv_bfloat162 a1 = __floats2bfloat162_rn(va.z, va.w);
                hA[i*2]   = *reinterpret_cast<uint32_t*>(&a0);
                hA[i*2+1] = *reinterpret_cast<uint32_t*>(&a1);
                float4 vb = *(const float4*)(srcB + i*16);
                sqAcc += vb.x*vb.x + vb.y*vb.y + vb.z*vb.z + vb.w*vb.w;
                __nv_bfloat162 b0 = __floats2bfloat162_rn(vb.x, vb.y);
                __nv_bfloat162 b1 = __floats2bfloat162_rn(vb.z, vb.w);
                hB[i*2]   = *reinterpret_cast<uint32_t*>(&b0);
                hB[i*2+1] = *reinterpret_cast<uint32_t*>(&b1);
            }
            char* dA = (char*)dsm + OFF_BA  + r0c*(SAELEM*2) + hc*32;
            char* dB = (char*)dsm + OFF_BB_ + r0c*(SAELEM*2) + hc*32;
            *(uint4*)dA      = make_uint4(hA[0],hA[1],hA[2],hA[3]);
            *(uint4*)(dA+16) = make_uint4(hA[4],hA[5],hA[6],hA[7]);
            *(uint4*)dB      = make_uint4(hB[0],hB[1],hB[2],hB[3]);
            *(uint4*)(dB+16) = make_uint4(hB[4],hB[5],hB[6],hB[7]);
        }
        __syncthreads();
        // refill raw stage st with chunk c+2
        if (c + 2 < DD/32)
            issue_chunk(Abase, Bbase, rawA[st], rawB[st], (c+2)*32, tid);
        CP_COMMIT();
        // mma on bf16 buffers
        #pragma unroll
        for (int ks = 0; ks < 2; ks++){
            uint32_t kb = ks*32;
            uint32_t a[2][4];
            #pragma unroll
            for (int i = 0; i < 2; i++)
                ldsm_x4(a[i], bAu + (wm*32 + i*16)*(SAELEM*2) + aRowOff + kb);
            uint32_t b[8][2];
            #pragma unroll
            for (int jj = 0; jj < 4; jj++){
                uint32_t r4[4];
                ldsm_x4(r4, bBu + (wn*64 + jj*16)*(SAELEM*2) + bRowOff + kb);
                b[jj*2][0] = r4[0]; b[jj*2][1] = r4[1];
                b[jj*2+1][0] = r4[2]; b[jj*2+1][1] = r4[3];
            }
            #pragma unroll
            for (int i = 0; i < 2; i++)
                #pragma unroll
                for (int j = 0; j < 8; j++)
                    mma16816(acc[i][j], a[i], b[j]);
        }
    }

    // cn2: combine the two halves of each row
    {
        float sq = sqAcc + __shfl_xor_sync(0xffffffffu, sqAcc, 1);
        if (hc == 0) s_cn2[r0c] = sq;
    }
    __syncthreads();

    // epilogue
    const int g = lane >> 2, tig = lane & 3;
    #pragma unroll
    for (int i = 0; i < 2; i++){
        int r0 = wm*32 + i*16 + g;
        int r1 = r0 + 8;
        float fn0 = g_fn2[p*BB + r0];
        float fn1 = g_fn2[p*BB + r1];
        float part0 = 0.f, part1 = 0.f;
        #pragma unroll
        for (int j = 0; j < 8; j++){
            int n = wn*64 + j*8 + tig*2;
            float mk0 = s_mask[n],   mk1 = s_mask[n+1];
            float cn0 = s_cn2[n],    cn1 = s_cn2[n+1];
            float d00 = fn0 + cn0 - 2.f*acc[i][j][0];
            float d01 = fn0 + cn1 - 2.f*acc[i][j][1];
            float d10 = fn1 + cn0 - 2.f*acc[i][j][2];
            float d11 = fn1 + cn1 - 2.f*acc[i][j][3];
            part0 += mk0*__expf(-SCALE_F*sqrtf(fmaxf(d00,1e-12f)))
                   + mk1*__expf(-SCALE_F*sqrtf(fmaxf(d01,1e-12f)));
            part1 += mk0*__expf(-SCALE_F*sqrtf(fmaxf(d10,1e-12f)))
                   + mk1*__expf(-SCALE_F*sqrtf(fmaxf(d11,1e-12f)));
        }
        part0 += __shfl_xor_sync(0xffffffffu, part0, 1);
        part0 += __shfl_xor_sync(0xffffffffu, part0, 2);
        part1 += __shfl_xor_sync(0xffffffffu, part1, 1);
        part1 += __shfl_xor_sync(0xffffffffu, part1, 2);
        if (tig == 0){
            s_red[r0*2 + wn] = part0;
            s_red[r1*2 + wn] = part1;
        }
    }
    __syncthreads();
    if (tid < BB)
        g_partial[((size_t)p*NT + tile)*BB + tid] = s_red[tid*2] + s_red[tid*2+1];
}

// ---------------- positive term ----------------------------------------------
__global__ void pos_kernel(const float* __restrict__ feature,
                           const float* __restrict__ centers,
                           const int* __restrict__ cross_indices){
    int p = blockIdx.x / BB, b = blockIdx.x % BB;
    int lane = threadIdx.x;
    const float* f = feature + (size_t)(p*BB+b)*DD;
    float fn2 = g_fn2[p*BB+b];
    float ssum = 0.f;
    for (int k = 0; k < KKc; k++){
        int idx = cross_indices[b*KKc + k];
        const float* c = centers + ((size_t)p*NN + idx)*DD;
        float dot = 0.f, sqv = 0.f;
        for (int d = lane; d < DD; d += 32){
            float cv = c[d];
            dot += f[d]*cv;
            sqv += cv*cv;
        }
        dot = warpSum(dot);
        sqv = warpSum(sqv);
        float pd2 = fn2 + sqv - 2.f*dot;
        float dist = sqrtf(fmaxf(pd2, 1e-12f));
        ssum += expf(-SCALE_F * dist);
    }
    if (lane == 0) g_x[p*BB+b] = logf(ssum);
}

// ---------------- pos_vid gather ---------------------------------------------
__global__ void posvid_kernel(const int* __restrict__ cross_indices,
                              const int* __restrict__ vid,
                              float* __restrict__ out, int out_size){
    int i = blockIdx.x*blockDim.x + threadIdx.x;
    if (i < BB*KKc && (3 + i) < out_size)
        out[3 + i] = (float)vid[cross_indices[i]];
}

// ---------------- final combine ----------------------------------------------
__global__ void final_kernel(float* __restrict__ out, int out_size){
    int b = threadIdx.x;
    float closs = 0.f;
    for (int p = 0; p < PP; p++){
        float ns = 0.f;
        for (int t = 0; t < NT; t++)
            ns += g_partial[((size_t)p*NT + t)*BB + b];
        float y = logf(ns);
        float v = y - g_x[p*BB + b];
        float s = blockSum128(v);
        float lp = s / (float)BB;
        if (isnan(lp)) lp = 0.f;
        closs += lp;
    }
    closs /= (float)PP;
    float aloss = 0.f;
    for (int p = 0; p < PP; p++){
        float nv = blockSum128((float)g_valid[p*BB + b]);
        float s1 = blockSum128(g_kl1[p*BB + b]);
        float s2 = blockSum128(g_kl2[p*BB + b]);
        float pp = 0.5f * (s1 + s2) / fmaxf(nv, 1.f);
        if (nv > 0.f) aloss += pp;
    }
    float klw = fmaxf(0.5f * (1.f - 1.f/60.f), 0.1f);
    float total = closs + klw * aloss;
    if (b == 0 && out_size >= 3){
        out[0] = total;
        out[1] = closs;
        out[2] = aloss;
    }
}

// ---------------- launch ------------------------------------------------------
extern "C" void kernel_launch(void* const* d_in, const int* in_sizes, int n_in,
                              void* d_out, int out_size){
    const float* feature       = (const float*)d_in[0];
    const float* text_feature  = (const float*)d_in[1];
    const float* centers       = (const float*)d_in[2];
    const int*   position      = (const int*)d_in[3];
    const int*   cross_indices = (const int*)d_in[4];
    const int*   vid           = (const int*)d_in[5];
    float* out = (float*)d_out;

    static bool attr_set = false;
    if (!attr_set){
        cudaFuncSetAttribute(neg_mma_kernel, cudaFuncAttributeMaxDynamicSharedMemorySize, NEG_SMEM);
        attr_set = true;
    }

    normalize_kernel<<<PP*BB, 128>>>(feature, text_feature);       // + mask init
    sim3_kernel<<<dim3(PP, 4, 2), 256>>>(feature, text_feature);
    valid_kernel<<<PP*BB, 128>>>(cross_indices, position);         // + mask scatter
    kl_kernel<<<PP*BB, 128>>>();
    neg_mma_kernel<<<dim3(NT, PP), 256, NEG_SMEM>>>(feature, centers);
    pos_kernel<<<PP*BB, 32>>>(feature, centers, cross_indices);
    posvid_kernel<<<(BB*KKc + 255)/256, 256>>>(cross_indices, vid, out, out_size);
    final_kernel<<<1, 128>>>(out, out_size);
}